// round 1
// baseline (speedup 1.0000x reference)
#include <cuda_runtime.h>
#include <math_constants.h>

// RGAT fused kernel: 4-layer GATv2 on 15552 independent 17-node graphs.
// One CTA processes 4 graphs (68 rows x 128 ch) through the ENTIRE network in SMEM.
// GEMMs use packed f32x2 FFMA (2x fp32 throughput on sm_100a).

#define NGRAPH 15552
#define GPB    4
#define ROWS   68      // GPB * 17
#define RPAD   72
#define NC     128

typedef unsigned long long ull;

// ---- packed f32x2 helpers ----
__device__ __forceinline__ ull pk2(float lo, float hi) {
    ull r;
    asm("mov.b64 %0, {%1, %2};" : "=l"(r)
        : "r"(__float_as_uint(lo)), "r"(__float_as_uint(hi)));
    return r;
}
__device__ __forceinline__ ull f2fma(ull a, ull b, ull c) {
    ull d;
    asm("fma.rn.f32x2 %0, %1, %2, %3;" : "=l"(d) : "l"(a), "l"(b), "l"(c));
    return d;
}
__device__ __forceinline__ float2 upk2(ull v) {
    unsigned u0, u1;
    asm("mov.b64 {%0, %1}, %2;" : "=r"(u0), "=r"(u1) : "l"(v));
    float2 f; f.x = __uint_as_float(u0); f.y = __uint_as_float(u1);
    return f;
}

// ---- hardcoded skeleton adjacency (deduped: 32 directed edges) ----
// Duplicated edges in the reference (64) are exactly equivalent under
// segment-softmax to this 32-edge list.
__constant__ signed char cESRC[32] = {0,0,0,1,1,2,2,3,4,4,5,5,6,7,7,8,8,8,8,9,9,10,11,11,12,12,13,14,14,15,15,16};
__constant__ signed char cEDST[32] = {1,4,7,0,2,1,3,2,0,5,4,6,5,0,8,7,9,11,14,8,10,9,8,12,11,13,12,8,15,14,16,15};
__constant__ signed char cIN_CNT[17] = {3,2,2,1,2,2,1,2,4,2,1,2,2,1,2,2,1};
__constant__ signed char cIN_EIDX[17][4] = {
    {3,8,13,0},{0,5,0,0},{4,7,0,0},{6,0,0,0},{1,10,0,0},{9,12,0,0},{11,0,0,0},{2,15,0,0},
    {14,19,22,27},{16,21,0,0},{20,0,0,0},{17,24,0,0},{23,26,0,0},{25,0,0,0},{18,29,0,0},
    {28,31,0,0},{30,0,0,0}};
__constant__ signed char cIN_SRC[17][4] = {
    {1,4,7,0},{0,2,0,0},{1,3,0,0},{2,0,0,0},{0,5,0,0},{4,6,0,0},{5,0,0,0},{0,8,0,0},
    {7,9,11,14},{8,10,0,0},{9,0,0,0},{8,12,0,0},{11,13,0,0},{12,0,0,0},{8,15,0,0},
    {14,16,0,0},{15,0,0,0}};

// SMEM layout (floats):
//  X0s  [68*128]  @ 0        = 8704
//  Hs   [72*128]  @ 8704     = 9216  (rows 68..71 zero)
//  XLs  [72*128]  @ 17920    = 9216
//  XRs  [72*128]  @ 27136    = 9216
//  WSl  [32*128]  @ 36352    = 4096
//  WSr  [32*128]  @ 40448    = 4096
//  ATTs [128]     @ 44544
//  BIs  [128]     @ 44672
//  LOGs [128]     @ 44800
//  AWs  [68*4]    @ 44928
// total = 45200 floats = 180800 bytes
#define SMEM_FLOATS 45200

extern "C" __global__ void __launch_bounds__(256, 1)
rgat_fused(const float* __restrict__ X,
           const float* __restrict__ gamma_, const float* __restrict__ beta_,
           const float* __restrict__ alpha_,
           const float* __restrict__ Wl, const float* __restrict__ blv,
           const float* __restrict__ Wr, const float* __restrict__ brv,
           const float* __restrict__ att, const float* __restrict__ bias_,
           float* __restrict__ out)
{
    extern __shared__ float sm[];
    float* X0s  = sm;
    float* Hs   = sm + 8704;
    float* XLs  = sm + 17920;
    float* XRs  = sm + 27136;
    float* WSl  = sm + 36352;
    float* WSr  = sm + 40448;
    float* ATTs = sm + 44544;
    float* BIs  = sm + 44672;
    float* LOGs = sm + 44800;
    float* AWs  = sm + 44928;

    const int tid  = threadIdx.x;
    const int lane = tid & 31;
    const int wrp  = tid >> 5;
    const size_t gbase = (size_t)blockIdx.x * (ROWS * NC);

    const float s   = 1.0f / (1.0f + expf(-alpha_[0]));
    const float oms = 1.0f - s;

    if (tid < NC) { ATTs[tid] = att[tid]; BIs[tid] = bias_[tid]; }
    // zero the pad rows of Hs once (attention never writes them)
    for (int i = tid; i < (RPAD - ROWS) * NC; i += 256) Hs[ROWS * NC + i] = 0.0f;

    // ---- load x + LayerNorm -> Hs, keep x in X0s ----
    {
        const float4* Xg = (const float4*)(X + gbase);
        const float4 g4 = ((const float4*)gamma_)[lane];
        const float4 b4 = ((const float4*)beta_)[lane];
        for (int r = wrp; r < ROWS; r += 8) {
            float4 v = Xg[r * 32 + lane];
            ((float4*)X0s)[r * 32 + lane] = v;
            float t = v.x + v.y + v.z + v.w;
            #pragma unroll
            for (int o = 16; o > 0; o >>= 1) t += __shfl_xor_sync(0xffffffffu, t, o);
            float mu = t * (1.0f / 128.0f);
            float dx = v.x - mu, dy = v.y - mu, dz = v.z - mu, dw = v.w - mu;
            float q = dx * dx + dy * dy + dz * dz + dw * dw;
            #pragma unroll
            for (int o = 16; o > 0; o >>= 1) q += __shfl_xor_sync(0xffffffffu, q, o);
            float rstd = rsqrtf(q * (1.0f / 128.0f) + 1e-5f);
            float4 hv;
            hv.x = dx * rstd * g4.x + b4.x;
            hv.y = dy * rstd * g4.y + b4.y;
            hv.z = dz * rstd * g4.z + b4.z;
            hv.w = dw * rstd * g4.w + b4.w;
            ((float4*)Hs)[r * 32 + lane] = hv;
        }
    }

    const float4 bl4 = ((const float4*)blv)[lane];
    const float4 br4 = ((const float4*)brv)[lane];
    const int r0 = wrp * 9;   // 8 warps x 9 rows = 72 rows

    __syncthreads();

    for (int layer = 0; layer < 4; ++layer) {
        // ================= GEMM: XL = Hs@Wl + bl, XR = Hs@Wr + br =============
        // thread tile: 9 rows (r0..r0+8) x 4 cols (4*lane..4*lane+3), both mats
        ull aL0[9], aL1[9], aR0[9], aR1[9];
        #pragma unroll
        for (int r = 0; r < 9; ++r) { aL0[r] = 0; aL1[r] = 0; aR0[r] = 0; aR1[r] = 0; }

        for (int kc = 0; kc < NC; kc += 32) {
            __syncthreads();   // previous chunk's WS reads (or prev layer h writes) done
            const float4* wlg = (const float4*)(Wl + kc * NC);
            const float4* wrg = (const float4*)(Wr + kc * NC);
            #pragma unroll
            for (int i = 0; i < 4; ++i) {
                ((float4*)WSl)[tid + 256 * i] = wlg[tid + 256 * i];
                ((float4*)WSr)[tid + 256 * i] = wrg[tid + 256 * i];
            }
            __syncthreads();
            const float* hb = Hs + r0 * NC + kc;
            #pragma unroll 8
            for (int k = 0; k < 32; ++k) {
                float4 wl = ((const float4*)WSl)[(k << 5) + lane];
                float4 wr = ((const float4*)WSr)[(k << 5) + lane];
                ull wl01 = pk2(wl.x, wl.y), wl23 = pk2(wl.z, wl.w);
                ull wr01 = pk2(wr.x, wr.y), wr23 = pk2(wr.z, wr.w);
                #pragma unroll
                for (int r = 0; r < 9; ++r) {
                    float a = hb[r * NC + k];   // warp-broadcast LDS
                    ull a2 = pk2(a, a);
                    aL0[r] = f2fma(a2, wl01, aL0[r]);
                    aL1[r] = f2fma(a2, wl23, aL1[r]);
                    aR0[r] = f2fma(a2, wr01, aR0[r]);
                    aR1[r] = f2fma(a2, wr23, aR1[r]);
                }
            }
        }
        #pragma unroll
        for (int r = 0; r < 9; ++r) {
            float2 l0 = upk2(aL0[r]), l1 = upk2(aL1[r]);
            float2 q0 = upk2(aR0[r]), q1 = upk2(aR1[r]);
            float4 ov;
            ov.x = l0.x + bl4.x; ov.y = l0.y + bl4.y; ov.z = l1.x + bl4.z; ov.w = l1.y + bl4.w;
            ((float4*)XLs)[(r0 + r) * 32 + lane] = ov;
            ov.x = q0.x + br4.x; ov.y = q0.y + br4.y; ov.z = q1.x + br4.z; ov.w = q1.y + br4.w;
            ((float4*)XRs)[(r0 + r) * 32 + lane] = ov;
        }
        __syncthreads();

        // ================= edge logits (128 edge-graph pairs, warp per dot) ===
        {
            const float4 a4 = ((const float4*)ATTs)[lane];
            for (int eg = wrp; eg < GPB * 32; eg += 8) {
                int g = eg >> 5, e = eg & 31;
                int rs = g * 17 + (int)cESRC[e];
                int rd = g * 17 + (int)cEDST[e];
                float4 vs = ((const float4*)XLs)[rs * 32 + lane];
                float4 vd = ((const float4*)XRs)[rd * 32 + lane];
                float t, acc = 0.0f;
                t = vs.x + vd.x; acc += (t > 0.0f ? t : 0.2f * t) * a4.x;
                t = vs.y + vd.y; acc += (t > 0.0f ? t : 0.2f * t) * a4.y;
                t = vs.z + vd.z; acc += (t > 0.0f ? t : 0.2f * t) * a4.z;
                t = vs.w + vd.w; acc += (t > 0.0f ? t : 0.2f * t) * a4.w;
                #pragma unroll
                for (int o = 16; o > 0; o >>= 1) acc += __shfl_xor_sync(0xffffffffu, acc, o);
                if (lane == 0) LOGs[eg] = acc;
            }
        }
        __syncthreads();

        // ================= per-node softmax weights ==========================
        if (tid < ROWS) {
            int g = tid / 17, j = tid - g * 17;
            int cnt = (int)cIN_CNT[j];
            float lv[4];
            #pragma unroll
            for (int i = 0; i < 4; ++i)
                lv[i] = (i < cnt) ? LOGs[g * 32 + (int)cIN_EIDX[j][i]] : -CUDART_INF_F;
            float m = fmaxf(fmaxf(lv[0], lv[1]), fmaxf(lv[2], lv[3]));
            float w0 = expf(lv[0] - m), w1 = expf(lv[1] - m);
            float w2 = expf(lv[2] - m), w3 = expf(lv[3] - m);  // pads -> exp(-inf)=0
            float inv = 1.0f / (w0 + w1 + w2 + w3);
            AWs[tid * 4 + 0] = w0 * inv; AWs[tid * 4 + 1] = w1 * inv;
            AWs[tid * 4 + 2] = w2 * inv; AWs[tid * 4 + 3] = w3 * inv;
        }
        __syncthreads();

        // ================= aggregate + residual -> Hs ========================
        for (int idx = tid; idx < ROWS * NC; idx += 256) {
            int r = idx >> 7, c = idx & 127;
            int g = r / 17, j = r - g * 17;
            int nb = g * 17;
            float acc = BIs[c];
            acc += AWs[r * 4 + 0] * XLs[(nb + (int)cIN_SRC[j][0]) * NC + c];
            acc += AWs[r * 4 + 1] * XLs[(nb + (int)cIN_SRC[j][1]) * NC + c];
            acc += AWs[r * 4 + 2] * XLs[(nb + (int)cIN_SRC[j][2]) * NC + c];
            acc += AWs[r * 4 + 3] * XLs[(nb + (int)cIN_SRC[j][3]) * NC + c];
            Hs[idx] = (layer == 0) ? acc : oms * acc + s * X0s[idx];
        }
        __syncthreads();
    }

    // ---- out = x + h ----
    float4* Og = (float4*)(out + gbase);
    for (int i = tid; i < ROWS * 32; i += 256) {
        float4 h4 = ((const float4*)Hs)[i];
        float4 x4 = ((const float4*)X0s)[i];
        float4 o4;
        o4.x = h4.x + x4.x; o4.y = h4.y + x4.y;
        o4.z = h4.z + x4.z; o4.w = h4.w + x4.w;
        Og[i] = o4;
    }
}

extern "C" void kernel_launch(void* const* d_in, const int* in_sizes, int n_in,
                              void* d_out, int out_size) {
    const float* X     = (const float*)d_in[0];
    const float* gam   = (const float*)d_in[1];
    const float* bet   = (const float*)d_in[2];
    const float* alp   = (const float*)d_in[3];
    const float* Wl    = (const float*)d_in[4];
    const float* bl    = (const float*)d_in[5];
    const float* Wr    = (const float*)d_in[6];
    const float* br    = (const float*)d_in[7];
    const float* att   = (const float*)d_in[8];
    const float* bias  = (const float*)d_in[9];
    float* out = (float*)d_out;

    (void)in_sizes; (void)n_in; (void)out_size;

    cudaFuncSetAttribute(rgat_fused, cudaFuncAttributeMaxDynamicSharedMemorySize,
                         SMEM_FLOATS * 4);
    rgat_fused<<<NGRAPH / GPB, 256, SMEM_FLOATS * 4>>>(
        X, gam, bet, alp, Wl, bl, Wr, br, att, bias, out);
}

// round 2
// speedup vs baseline: 1.0404x; 1.0404x over previous
#include <cuda_runtime.h>
#include <math_constants.h>

// RGAT fused kernel v2: 4-layer GATv2 on 15552 independent 17-node graphs.
// One CTA (512 thr, 16 warps) processes 4 graphs (68 rows x 128 ch) through the
// ENTIRE network in SMEM. GEMMs use packed f32x2 FFMA. Double-buffered W tiles.

#define NGRAPH 15552
#define GPB    4
#define ROWS   68      // GPB * 17
#define RPAD   80      // 16 warps x 5 rows
#define NC     128
#define NTHR   512

typedef unsigned long long ull;

// ---- packed f32x2 helpers ----
__device__ __forceinline__ ull pk2(float lo, float hi) {
    ull r;
    asm("mov.b64 %0, {%1, %2};" : "=l"(r)
        : "r"(__float_as_uint(lo)), "r"(__float_as_uint(hi)));
    return r;
}
__device__ __forceinline__ ull f2fma(ull a, ull b, ull c) {
    ull d;
    asm("fma.rn.f32x2 %0, %1, %2, %3;" : "=l"(d) : "l"(a), "l"(b), "l"(c));
    return d;
}
__device__ __forceinline__ float2 upk2(ull v) {
    unsigned u0, u1;
    asm("mov.b64 {%0, %1}, %2;" : "=r"(u0), "=r"(u1) : "l"(v));
    float2 f; f.x = __uint_as_float(u0); f.y = __uint_as_float(u1);
    return f;
}

// ---- hardcoded skeleton adjacency (deduped: 32 directed edges) ----
// Duplicated edges in the reference (64) are exactly equivalent under
// segment-softmax to this 32-edge list.
__constant__ signed char cESRC[32] = {0,0,0,1,1,2,2,3,4,4,5,5,6,7,7,8,8,8,8,9,9,10,11,11,12,12,13,14,14,15,15,16};
__constant__ signed char cEDST[32] = {1,4,7,0,2,1,3,2,0,5,4,6,5,0,8,7,9,11,14,8,10,9,8,12,11,13,12,8,15,14,16,15};
__constant__ signed char cIN_CNT[17] = {3,2,2,1,2,2,1,2,4,2,1,2,2,1,2,2,1};
__constant__ signed char cIN_EIDX[17][4] = {
    {3,8,13,0},{0,5,0,0},{4,7,0,0},{6,0,0,0},{1,10,0,0},{9,12,0,0},{11,0,0,0},{2,15,0,0},
    {14,19,22,27},{16,21,0,0},{20,0,0,0},{17,24,0,0},{23,26,0,0},{25,0,0,0},{18,29,0,0},
    {28,31,0,0},{30,0,0,0}};
__constant__ signed char cIN_SRC[17][4] = {
    {1,4,7,0},{0,2,0,0},{1,3,0,0},{2,0,0,0},{0,5,0,0},{4,6,0,0},{5,0,0,0},{0,8,0,0},
    {7,9,11,14},{8,10,0,0},{9,0,0,0},{8,12,0,0},{11,13,0,0},{12,0,0,0},{8,15,0,0},
    {14,16,0,0},{15,0,0,0}};

// SMEM layout (floats):
//  X0s  [68*128]    @ 0      = 8704
//  Hs   [80*128]    @ 8704   = 10240  (rows 68..79 zero)
//  XLs  [80*128]    @ 18944  = 10240
//  XRs  [80*128]    @ 29184  = 10240
//  WSl  [2*32*128]  @ 39424  = 8192   (double buffer)
//  WSr  [2*32*128]  @ 47616  = 8192
//  ATTs [128]       @ 55808
//  BIs  [128]       @ 55936
//  LOGs [128]       @ 56064
//  AWs  [68*4]      @ 56192  = 272
#define SMEM_FLOATS 56464

extern "C" __global__ void __launch_bounds__(NTHR, 1)
rgat_fused(const float* __restrict__ X,
           const float* __restrict__ gamma_, const float* __restrict__ beta_,
           const float* __restrict__ alpha_,
           const float* __restrict__ Wl, const float* __restrict__ blv,
           const float* __restrict__ Wr, const float* __restrict__ brv,
           const float* __restrict__ att, const float* __restrict__ bias_,
           float* __restrict__ out)
{
    extern __shared__ float sm[];
    float* X0s  = sm;
    float* Hs   = sm + 8704;
    float* XLs  = sm + 18944;
    float* XRs  = sm + 29184;
    float* WSl  = sm + 39424;
    float* WSr  = sm + 47616;
    float* ATTs = sm + 55808;
    float* BIs  = sm + 55936;
    float* LOGs = sm + 56064;
    float* AWs  = sm + 56192;

    const int tid  = threadIdx.x;
    const int lane = tid & 31;
    const int wrp  = tid >> 5;
    const size_t gbase = (size_t)blockIdx.x * (ROWS * NC);

    const float s   = 1.0f / (1.0f + expf(-alpha_[0]));
    const float oms = 1.0f - s;

    if (tid < NC) { ATTs[tid] = att[tid]; BIs[tid] = bias_[tid]; }
    // zero the pad rows of Hs once (attention never writes them)
    for (int i = tid; i < (RPAD - ROWS) * NC; i += NTHR) Hs[ROWS * NC + i] = 0.0f;

    // ---- load x + LayerNorm -> Hs, keep x in X0s ----
    {
        const float4* Xg = (const float4*)(X + gbase);
        const float4 g4 = ((const float4*)gamma_)[lane];
        const float4 b4 = ((const float4*)beta_)[lane];
        for (int r = wrp; r < ROWS; r += 16) {
            float4 v = Xg[r * 32 + lane];
            ((float4*)X0s)[r * 32 + lane] = v;
            float t = v.x + v.y + v.z + v.w;
            #pragma unroll
            for (int o = 16; o > 0; o >>= 1) t += __shfl_xor_sync(0xffffffffu, t, o);
            float mu = t * (1.0f / 128.0f);
            float dx = v.x - mu, dy = v.y - mu, dz = v.z - mu, dw = v.w - mu;
            float q = dx * dx + dy * dy + dz * dz + dw * dw;
            #pragma unroll
            for (int o = 16; o > 0; o >>= 1) q += __shfl_xor_sync(0xffffffffu, q, o);
            float rstd = rsqrtf(q * (1.0f / 128.0f) + 1e-5f);
            float4 hv;
            hv.x = dx * rstd * g4.x + b4.x;
            hv.y = dy * rstd * g4.y + b4.y;
            hv.z = dz * rstd * g4.z + b4.z;
            hv.w = dw * rstd * g4.w + b4.w;
            ((float4*)Hs)[r * 32 + lane] = hv;
        }
    }

    // ---- prefetch W chunk 0 into buffer 0 ----
    {
        const float4* wlg = (const float4*)Wl;
        const float4* wrg = (const float4*)Wr;
        #pragma unroll
        for (int i = 0; i < 2; ++i) {
            ((float4*)WSl)[tid + NTHR * i] = wlg[tid + NTHR * i];
            ((float4*)WSr)[tid + NTHR * i] = wrg[tid + NTHR * i];
        }
    }

    const float4 bl4 = ((const float4*)blv)[lane];
    const float4 br4 = ((const float4*)brv)[lane];
    const int r0 = wrp * 5;   // 16 warps x 5 rows = 80 rows

    __syncthreads();

    int q = 0;  // global chunk counter (layer*4 + chunk), parity = buffer id
    for (int layer = 0; layer < 4; ++layer) {
        // ================= GEMM: XL = Hs@Wl + bl, XR = Hs@Wr + br =============
        // thread tile: 5 rows (r0..r0+4) x 4 cols (4*lane..), both matrices
        ull aL0[5], aL1[5], aR0[5], aR1[5];
        #pragma unroll
        for (int r = 0; r < 5; ++r) { aL0[r] = 0; aL1[r] = 0; aR0[r] = 0; aR1[r] = 0; }

        for (int c = 0; c < 4; ++c, ++q) {
            __syncthreads();   // buf (q&1) writes visible; prior reads of buf ((q+1)&1) done
            // prefetch next chunk into the other buffer (W identical every layer)
            if (q < 15) {
                const int kcn = ((q + 1) & 3) * 32;
                const float4* wlg = (const float4*)(Wl + kcn * NC);
                const float4* wrg = (const float4*)(Wr + kcn * NC);
                float* dl = WSl + ((q + 1) & 1) * 4096;
                float* dr = WSr + ((q + 1) & 1) * 4096;
                #pragma unroll
                for (int i = 0; i < 2; ++i) {
                    ((float4*)dl)[tid + NTHR * i] = wlg[tid + NTHR * i];
                    ((float4*)dr)[tid + NTHR * i] = wrg[tid + NTHR * i];
                }
            }
            const float* wsl = WSl + (q & 1) * 4096;
            const float* wsr = WSr + (q & 1) * 4096;
            const float* hb  = Hs + r0 * NC + c * 32;
            #pragma unroll 4
            for (int k4 = 0; k4 < 32; k4 += 4) {
                float4 a4[5];
                #pragma unroll
                for (int r = 0; r < 5; ++r)
                    a4[r] = *(const float4*)(hb + r * NC + k4);   // broadcast LDS.128
                #pragma unroll
                for (int kk = 0; kk < 4; ++kk) {
                    float4 wl = ((const float4*)wsl)[((k4 + kk) << 5) + lane];
                    float4 wr = ((const float4*)wsr)[((k4 + kk) << 5) + lane];
                    ull wl01 = pk2(wl.x, wl.y), wl23 = pk2(wl.z, wl.w);
                    ull wr01 = pk2(wr.x, wr.y), wr23 = pk2(wr.z, wr.w);
                    #pragma unroll
                    for (int r = 0; r < 5; ++r) {
                        float a = (kk == 0) ? a4[r].x : (kk == 1) ? a4[r].y
                                : (kk == 2) ? a4[r].z : a4[r].w;
                        ull a2 = pk2(a, a);
                        aL0[r] = f2fma(a2, wl01, aL0[r]);
                        aL1[r] = f2fma(a2, wl23, aL1[r]);
                        aR0[r] = f2fma(a2, wr01, aR0[r]);
                        aR1[r] = f2fma(a2, wr23, aR1[r]);
                    }
                }
            }
        }
        #pragma unroll
        for (int r = 0; r < 5; ++r) {
            float2 l0 = upk2(aL0[r]), l1 = upk2(aL1[r]);
            float2 q0 = upk2(aR0[r]), q1 = upk2(aR1[r]);
            float4 ov;
            ov.x = l0.x + bl4.x; ov.y = l0.y + bl4.y; ov.z = l1.x + bl4.z; ov.w = l1.y + bl4.w;
            ((float4*)XLs)[(r0 + r) * 32 + lane] = ov;
            ov.x = q0.x + br4.x; ov.y = q0.y + br4.y; ov.z = q1.x + br4.z; ov.w = q1.y + br4.w;
            ((float4*)XRs)[(r0 + r) * 32 + lane] = ov;
        }
        __syncthreads();

        // ================= edge logits (128 edge-graph pairs, warp per dot) ===
        {
            const float4 a4 = ((const float4*)ATTs)[lane];
            for (int eg = wrp; eg < GPB * 32; eg += 16) {
                int g = eg >> 5, e = eg & 31;
                int rs = g * 17 + (int)cESRC[e];
                int rd = g * 17 + (int)cEDST[e];
                float4 vs = ((const float4*)XLs)[rs * 32 + lane];
                float4 vd = ((const float4*)XRs)[rd * 32 + lane];
                float t, acc = 0.0f;
                t = vs.x + vd.x; acc += (t > 0.0f ? t : 0.2f * t) * a4.x;
                t = vs.y + vd.y; acc += (t > 0.0f ? t : 0.2f * t) * a4.y;
                t = vs.z + vd.z; acc += (t > 0.0f ? t : 0.2f * t) * a4.z;
                t = vs.w + vd.w; acc += (t > 0.0f ? t : 0.2f * t) * a4.w;
                #pragma unroll
                for (int o = 16; o > 0; o >>= 1) acc += __shfl_xor_sync(0xffffffffu, acc, o);
                if (lane == 0) LOGs[eg] = acc;
            }
        }
        __syncthreads();

        // ================= per-node softmax weights ==========================
        if (tid < ROWS) {
            int g = tid / 17, j = tid - g * 17;
            int cnt = (int)cIN_CNT[j];
            float lv[4];
            #pragma unroll
            for (int i = 0; i < 4; ++i)
                lv[i] = (i < cnt) ? LOGs[g * 32 + (int)cIN_EIDX[j][i]] : -CUDART_INF_F;
            float m = fmaxf(fmaxf(lv[0], lv[1]), fmaxf(lv[2], lv[3]));
            float w0 = expf(lv[0] - m), w1 = expf(lv[1] - m);
            float w2 = expf(lv[2] - m), w3 = expf(lv[3] - m);  // pads -> exp(-inf)=0
            float inv = 1.0f / (w0 + w1 + w2 + w3);
            AWs[tid * 4 + 0] = w0 * inv; AWs[tid * 4 + 1] = w1 * inv;
            AWs[tid * 4 + 2] = w2 * inv; AWs[tid * 4 + 3] = w3 * inv;
        }
        __syncthreads();

        // ================= aggregate + residual -> Hs ========================
        for (int idx = tid; idx < ROWS * NC; idx += NTHR) {
            int r = idx >> 7, cc = idx & 127;
            int g = r / 17, j = r - g * 17;
            int nb = g * 17;
            float acc = BIs[cc];
            acc += AWs[r * 4 + 0] * XLs[(nb + (int)cIN_SRC[j][0]) * NC + cc];
            acc += AWs[r * 4 + 1] * XLs[(nb + (int)cIN_SRC[j][1]) * NC + cc];
            acc += AWs[r * 4 + 2] * XLs[(nb + (int)cIN_SRC[j][2]) * NC + cc];
            acc += AWs[r * 4 + 3] * XLs[(nb + (int)cIN_SRC[j][3]) * NC + cc];
            Hs[idx] = (layer == 0) ? acc : oms * acc + s * X0s[idx];
        }
        __syncthreads();
    }

    // ---- out = x + h ----
    float4* Og = (float4*)(out + gbase);
    for (int i = tid; i < ROWS * 32; i += NTHR) {
        float4 h4 = ((const float4*)Hs)[i];
        float4 x4 = ((const float4*)X0s)[i];
        float4 o4;
        o4.x = h4.x + x4.x; o4.y = h4.y + x4.y;
        o4.z = h4.z + x4.z; o4.w = h4.w + x4.w;
        Og[i] = o4;
    }
}

extern "C" void kernel_launch(void* const* d_in, const int* in_sizes, int n_in,
                              void* d_out, int out_size) {
    const float* X     = (const float*)d_in[0];
    const float* gam   = (const float*)d_in[1];
    const float* bet   = (const float*)d_in[2];
    const float* alp   = (const float*)d_in[3];
    const float* Wl    = (const float*)d_in[4];
    const float* bl    = (const float*)d_in[5];
    const float* Wr    = (const float*)d_in[6];
    const float* br    = (const float*)d_in[7];
    const float* att   = (const float*)d_in[8];
    const float* bias  = (const float*)d_in[9];
    float* out = (float*)d_out;

    (void)in_sizes; (void)n_in; (void)out_size;

    cudaFuncSetAttribute(rgat_fused, cudaFuncAttributeMaxDynamicSharedMemorySize,
                         SMEM_FLOATS * 4);
    rgat_fused<<<NGRAPH / GPB, NTHR, SMEM_FLOATS * 4>>>(
        X, gam, bet, alp, Wl, bl, Wr, br, att, bias, out);
}

// round 5
// speedup vs baseline: 2.2085x; 2.1228x over previous
#include <cuda_runtime.h>
#include <cuda_fp16.h>
#include <math_constants.h>
#include <cstdint>

// RGAT v4: legacy HMMA (mma.sync m16n8k16 f16) GEMMs, fragment-layout SMEM,
// fused 4-layer GATv2, 5 graphs/CTA. No tcgen05 (target is plain sm_100).
#define NGRAPH 15552
#define GPB    5
#define NCTA   3111          // ceil(15552/5)
#define NC     128
#define NTHR   512
#define MPAD   96            // 6 m16-tiles
#define XLST   132           // padded fp32 row stride (floats)

// SMEM byte offsets
#define OFF_XL   0                       // 96*132*4 = 50688
#define OFF_XR   50688                   // 50688
#define OFF_AH   101376                  // A-frags: [part2][mt6][kt8][lane32][16B] = 49152
#define AH_PART  24576                   // part stride (6*8*32*16)
#define OFF_WB   150528                  // B-frags: [mat2][kt8][nt8:16][lane32][8B] = 65536
#define OFF_ATT  216064                  // 512
#define OFF_BI   216576                  // 512
#define OFF_BL   217088                  // 512
#define OFF_BR   217600                  // 512
#define OFF_LOG  218112                  // 160*4 = 640
#define OFF_AW   218752                  // 85*4*4 = 1360
#define SMEM_REQ 220160

// ---- skeleton adjacency (deduped 32 directed edges; duplicates in the
// reference are mathematically identical under segment softmax) ----
__constant__ signed char cESRC[32] = {0,0,0,1,1,2,2,3,4,4,5,5,6,7,7,8,8,8,8,9,9,10,11,11,12,12,13,14,14,15,15,16};
__constant__ signed char cEDST[32] = {1,4,7,0,2,1,3,2,0,5,4,6,5,0,8,7,9,11,14,8,10,9,8,12,11,13,12,8,15,14,16,15};
__constant__ signed char cIN_CNT[17] = {3,2,2,1,2,2,1,2,4,2,1,2,2,1,2,2,1};
__constant__ signed char cIN_EIDX[17][4] = {
    {3,8,13,0},{0,5,0,0},{4,7,0,0},{6,0,0,0},{1,10,0,0},{9,12,0,0},{11,0,0,0},{2,15,0,0},
    {14,19,22,27},{16,21,0,0},{20,0,0,0},{17,24,0,0},{23,26,0,0},{25,0,0,0},{18,29,0,0},
    {28,31,0,0},{30,0,0,0}};
__constant__ signed char cIN_SRC[17][4] = {
    {1,4,7,0},{0,2,0,0},{1,3,0,0},{2,0,0,0},{0,5,0,0},{4,6,0,0},{5,0,0,0},{0,8,0,0},
    {7,9,11,14},{8,10,0,0},{9,0,0,0},{8,12,0,0},{11,13,0,0},{12,0,0,0},{8,15,0,0},
    {14,16,0,0},{15,0,0,0}};

__device__ __forceinline__ void mma16816(float* d, const uint32_t* a,
                                         uint32_t b0, uint32_t b1) {
    asm volatile("mma.sync.aligned.m16n8k16.row.col.f32.f16.f16.f32 "
        "{%0,%1,%2,%3}, {%4,%5,%6,%7}, {%8,%9}, {%0,%1,%2,%3};"
        : "+f"(d[0]), "+f"(d[1]), "+f"(d[2]), "+f"(d[3])
        : "r"(a[0]), "r"(a[1]), "r"(a[2]), "r"(a[3]), "r"(b0), "r"(b1));
}

// write one even channel-pair (ch, ch+1) of H row r into hi/lo A-fragment SMEM
__device__ __forceinline__ void storeHfrag(unsigned char* smb, int r, int ch,
                                           float v0, float v1) {
    __half h0 = __float2half(v0), h1 = __float2half(v1);
    __half l0 = __float2half(v0 - __half2float(h0));
    __half l1 = __float2half(v1 - __half2float(h1));
    uint32_t hi = ((uint32_t)__half_as_ushort(h1) << 16) | (uint32_t)__half_as_ushort(h0);
    uint32_t lo = ((uint32_t)__half_as_ushort(l1) << 16) | (uint32_t)__half_as_ushort(l0);
    int mt = r >> 4, rr = r & 15, kt = ch >> 4, kk = ch & 15;
    int ln  = (rr & 7) * 4 + ((kk >> 1) & 3);
    int reg = (rr >> 3) + 2 * (kk >> 3);
    uint32_t off = OFF_AH + (uint32_t)(((mt * 8 + kt) * 32 + ln) * 16 + reg * 4);
    *(uint32_t*)(smb + off)           = hi;
    *(uint32_t*)(smb + off + AH_PART) = lo;
}

extern "C" __global__ void __launch_bounds__(NTHR, 1)
rgat_hmma(const float* __restrict__ X,
          const float* __restrict__ gamma_, const float* __restrict__ beta_,
          const float* __restrict__ alpha_,
          const float* __restrict__ Wl, const float* __restrict__ blv,
          const float* __restrict__ Wr, const float* __restrict__ brv,
          const float* __restrict__ att, const float* __restrict__ bias_,
          float* __restrict__ out)
{
    extern __shared__ unsigned char smb[];
    float* XLs  = (float*)(smb + OFF_XL);
    float* XRs  = (float*)(smb + OFF_XR);
    float* ATTs = (float*)(smb + OFF_ATT);
    float* BIs  = (float*)(smb + OFF_BI);
    float* BLs  = (float*)(smb + OFF_BL);
    float* BRs  = (float*)(smb + OFF_BR);
    float* LOGs = (float*)(smb + OFF_LOG);
    float* AWs  = (float*)(smb + OFF_AW);

    const int tid  = threadIdx.x;
    const int lane = tid & 31;
    const int wrp  = tid >> 5;
    const int bid  = blockIdx.x;
    const int ngr  = min(GPB, NGRAPH - bid * GPB);
    const int rows = ngr * 17;
    const size_t gbase = (size_t)bid * (GPB * 17 * NC);

    const float s   = 1.0f / (1.0f + expf(-alpha_[0]));
    const float oms = 1.0f - s;

    // -------- prologue: consts, W -> B-frag layout (f16), LN(x) -> A-frags ----
    if (tid < NC) {
        ATTs[tid] = att[tid];  BIs[tid] = bias_[tid];
        BLs[tid]  = blv[tid];  BRs[tid] = brv[tid];
    }
    for (int idx = tid; idx < 2 * NC * NC; idx += NTHR) {
        int mat = idx >> 14, e = idx & 16383;
        int k = e >> 7, n = e & 127;
        float w = (mat ? Wr : Wl)[e];
        int kt = k >> 4, kk = k & 15, nt8 = n >> 3, g = n & 7;
        int ln  = g * 4 + ((kk >> 1) & 3);
        int reg = kk >> 3;
        uint32_t off = OFF_WB + (uint32_t)((((mat * 8 + kt) * 16 + nt8) * 32 + ln) * 8
                                           + reg * 4 + (kk & 1) * 2);
        *(__half*)(smb + off) = __float2half(w);
    }
    {
        const float4 g4 = ((const float4*)gamma_)[lane];
        const float4 b4 = ((const float4*)beta_)[lane];
        for (int r = wrp; r < rows; r += 16) {
            float4 v = ((const float4*)(X + gbase))[r * 32 + lane];
            float t = v.x + v.y + v.z + v.w;
            #pragma unroll
            for (int o = 16; o > 0; o >>= 1) t += __shfl_xor_sync(0xffffffffu, t, o);
            float mu = t * (1.0f / 128.0f);
            float dx = v.x - mu, dy = v.y - mu, dz = v.z - mu, dw = v.w - mu;
            float q = dx * dx + dy * dy + dz * dz + dw * dw;
            #pragma unroll
            for (int o = 16; o > 0; o >>= 1) q += __shfl_xor_sync(0xffffffffu, q, o);
            float rstd = rsqrtf(q * (1.0f / 128.0f) + 1e-5f);
            float h0 = dx * rstd * g4.x + b4.x;
            float h1 = dy * rstd * g4.y + b4.y;
            float h2 = dz * rstd * g4.z + b4.z;
            float h3 = dw * rstd * g4.w + b4.w;
            storeHfrag(smb, r, 4 * lane,     h0, h1);
            storeHfrag(smb, r, 4 * lane + 2, h2, h3);
        }
    }
    __syncthreads();

    for (int layer = 0; layer < 4; ++layer) {
        // ========== GEMM via HMMA: XL = H@Wl + bl, XR = H@Wr + br ==========
        // 48 warp-tiles (m16 x n32): mt(6) x nt(4) x mat(2); 3 tiles per warp.
        #pragma unroll 1
        for (int i = 0; i < 3; ++i) {
            const int t  = wrp + (i << 4);
            const int mt = t % 6;
            const int q  = t / 6;        // 0..7
            const int nt = q & 3;
            const int mat = q >> 2;

            uint4 Ah[8], Al[8];
            const unsigned char* abase = smb + OFF_AH + mt * (8 * 512) + lane * 16;
            #pragma unroll
            for (int kt = 0; kt < 8; ++kt) {
                Ah[kt] = *(const uint4*)(abase + kt * 512);
                Al[kt] = *(const uint4*)(abase + kt * 512 + AH_PART);
            }
            float acc[4][4];
            #pragma unroll
            for (int j = 0; j < 4; ++j)
                #pragma unroll
                for (int c = 0; c < 4; ++c) acc[j][c] = 0.0f;

            const unsigned char* bbase = smb + OFF_WB
                + (uint32_t)((mat * 8 * 16 + nt * 4) * 256) + lane * 8;
            #pragma unroll
            for (int kt = 0; kt < 8; ++kt) {
                #pragma unroll
                for (int j = 0; j < 4; ++j) {
                    uint2 b = *(const uint2*)(bbase + (kt * 16 + j) * 256);
                    mma16816(acc[j], (const uint32_t*)&Ah[kt], b.x, b.y);
                    mma16816(acc[j], (const uint32_t*)&Al[kt], b.x, b.y);
                }
            }
            // epilogue: += bias, store fp32 row-major (stride 132)
            float* dst = mat ? XRs : XLs;
            const float* bv = mat ? BRs : BLs;
            const int g = lane >> 2, tg = lane & 3;
            const int row0 = mt * 16 + g;
            #pragma unroll
            for (int j = 0; j < 4; ++j) {
                int col = nt * 32 + j * 8 + tg * 2;
                float2 bb = *(const float2*)(bv + col);
                float2 o0, o1;
                o0.x = acc[j][0] + bb.x; o0.y = acc[j][1] + bb.y;
                o1.x = acc[j][2] + bb.x; o1.y = acc[j][3] + bb.y;
                *(float2*)(dst + row0 * XLST + col)       = o0;
                *(float2*)(dst + (row0 + 8) * XLST + col) = o1;
            }
        }
        __syncthreads();

        // ========== edge logits (ngr*32 edge dots, warp each) ==========
        {
            const float4 a4 = ((const float4*)ATTs)[lane];
            for (int eg = wrp; eg < ngr * 32; eg += 16) {
                int g = eg >> 5, e = eg & 31;
                int rs = g * 17 + (int)cESRC[e];
                int rd = g * 17 + (int)cEDST[e];
                float4 vs = ((const float4*)XLs)[rs * 33 + lane];
                float4 vd = ((const float4*)XRs)[rd * 33 + lane];
                float t, acc = 0.0f;
                t = vs.x + vd.x; acc += (t > 0.0f ? t : 0.2f * t) * a4.x;
                t = vs.y + vd.y; acc += (t > 0.0f ? t : 0.2f * t) * a4.y;
                t = vs.z + vd.z; acc += (t > 0.0f ? t : 0.2f * t) * a4.z;
                t = vs.w + vd.w; acc += (t > 0.0f ? t : 0.2f * t) * a4.w;
                #pragma unroll
                for (int o = 16; o > 0; o >>= 1) acc += __shfl_xor_sync(0xffffffffu, acc, o);
                if (lane == 0) LOGs[eg] = acc;
            }
        }
        __syncthreads();

        // ========== per-node softmax ==========
        if (tid < rows) {
            int g = tid / 17, j = tid - g * 17;
            int cnt = (int)cIN_CNT[j];
            float lv[4];
            #pragma unroll
            for (int i = 0; i < 4; ++i)
                lv[i] = (i < cnt) ? LOGs[g * 32 + (int)cIN_EIDX[j][i]] : -CUDART_INF_F;
            float m = fmaxf(fmaxf(lv[0], lv[1]), fmaxf(lv[2], lv[3]));
            float w0 = expf(lv[0] - m), w1 = expf(lv[1] - m);
            float w2 = expf(lv[2] - m), w3 = expf(lv[3] - m);
            float inv = 1.0f / (w0 + w1 + w2 + w3);
            AWs[tid * 4 + 0] = w0 * inv; AWs[tid * 4 + 1] = w1 * inv;
            AWs[tid * 4 + 2] = w2 * inv; AWs[tid * 4 + 3] = w3 * inv;
        }
        __syncthreads();

        // ========== aggregate + residual ==========
        if (layer < 3) {
            for (int idx = tid; idx < rows * 64; idx += NTHR) {
                int r = idx >> 6, ch = (idx & 63) * 2;
                int g = r / 17, j = r - g * 17, nb = g * 17;
                float acc0 = BIs[ch], acc1 = BIs[ch + 1];
                #pragma unroll
                for (int i = 0; i < 4; ++i) {
                    float w = AWs[r * 4 + i];
                    float2 v = *(const float2*)(XLs + (nb + (int)cIN_SRC[j][i]) * XLST + ch);
                    acc0 += w * v.x; acc1 += w * v.y;
                }
                if (layer > 0) {
                    float2 x0 = *(const float2*)(X + gbase + r * NC + ch);
                    acc0 = oms * acc0 + s * x0.x;
                    acc1 = oms * acc1 + s * x0.y;
                }
                storeHfrag(smb, r, ch, acc0, acc1);
            }
        } else {
            for (int idx = tid; idx < rows * 64; idx += NTHR) {
                int r = idx >> 6, ch = (idx & 63) * 2;
                int g = r / 17, j = r - g * 17, nb = g * 17;
                float acc0 = BIs[ch], acc1 = BIs[ch + 1];
                #pragma unroll
                for (int i = 0; i < 4; ++i) {
                    float w = AWs[r * 4 + i];
                    float2 v = *(const float2*)(XLs + (nb + (int)cIN_SRC[j][i]) * XLST + ch);
                    acc0 += w * v.x; acc1 += w * v.y;
                }
                float2 x0 = *(const float2*)(X + gbase + r * NC + ch);
                float2 o;
                o.x = x0.x * (1.0f + s) + oms * acc0;
                o.y = x0.y * (1.0f + s) + oms * acc1;
                *(float2*)(out + gbase + r * NC + ch) = o;
            }
        }
        __syncthreads();
    }
}

extern "C" void kernel_launch(void* const* d_in, const int* in_sizes, int n_in,
                              void* d_out, int out_size) {
    const float* X    = (const float*)d_in[0];
    const float* gam  = (const float*)d_in[1];
    const float* bet  = (const float*)d_in[2];
    const float* alp  = (const float*)d_in[3];
    const float* Wl   = (const float*)d_in[4];
    const float* bl   = (const float*)d_in[5];
    const float* Wr   = (const float*)d_in[6];
    const float* br   = (const float*)d_in[7];
    const float* att  = (const float*)d_in[8];
    const float* bias = (const float*)d_in[9];
    float* out = (float*)d_out;
    (void)in_sizes; (void)n_in; (void)out_size;

    cudaFuncSetAttribute(rgat_hmma, cudaFuncAttributeMaxDynamicSharedMemorySize, SMEM_REQ);
    rgat_hmma<<<NCTA, NTHR, SMEM_REQ>>>(X, gam, bet, alp, Wl, bl, Wr, br, att, bias, out);
}